// round 16
// baseline (speedup 1.0000x reference)
#include <cuda_runtime.h>
#include <cuda_fp16.h>
#include <cstdint>
#include <cmath>

// Problem constants
#define BB   4
#define SS   1024
#define DD   1024
#define HH   16
#define DKH  64
#define LL   4
#define FF   4096
#define VV   32000
#define NT   (BB*SS)   // 4096 tokens
#define QKVW 3072      // packed q|k|v width

// GEMM tile config: CTA 128x128, warp 64x32 (2x4 warps), BK=64, 3-stage, 2 CTAs/SM
#define BM 128
#define BN 128
#define BK 64
#define AROWB 144                  // A smem row: 128B data + 16B pad
#define ASTG (BM*AROWB)            // one 128xBK fp16 matrix: 18432 B
#define BROWB 272                  // B smem row: 256B data + 16B pad
#define BSTG (64*BROWB)            // one 64x128 fp16 plane per stage: 17408 B
#define STG (ASTG + BSTG)          // 35840 B per stage
#define GEMM_SMEM (3*STG)          // 107520 B  (2 CTAs/SM: 215040 <= ~227KB)

// Attention smem
#define TROWB 144                  // 64 fp16 = 128B + 16B pad
#define TTILE (64*TROWB)           // 9216 B

// fp16 weight plane offsets (elements)
#define OFF_WQ   0
#define OFF_WK   (4*DD*DD)
#define OFF_WV   (8*DD*DD)
#define OFF_WO   (12*DD*DD)
#define OFF_W1   (16*DD*DD)
#define OFF_W2   (OFF_W1 + LL*DD*FF)
#define OFF_WOUT (OFF_W2 + LL*DD*FF)
#define WTOT     (OFF_WOUT + (size_t)DD*VV)   // 83,099,648 elems

// ---------------------------------------------------------------------------
// Scratch (device globals — no runtime allocation allowed)
// ---------------------------------------------------------------------------
__device__ float g_h  [NT*(size_t)DD];
__device__ float g_tmp[NT*(size_t)DD];
__device__ __half g_qh [NT*(size_t)QKVW];
__device__ __half g_ah [NT*(size_t)DD];
__device__ __half g_fh [NT*(size_t)FF];
__device__ __half g_wh [WTOT];

// ---------------------------------------------------------------------------
// PTX helpers
// ---------------------------------------------------------------------------
__device__ __forceinline__ uint32_t smem_u32(const void* p) {
    uint32_t a;
    asm("{ .reg .u64 t; cvta.to.shared.u64 t, %1; cvt.u32.u64 %0, t; }" : "=r"(a) : "l"(p));
    return a;
}
__device__ __forceinline__ void cp_async16(uint32_t dst, const void* src) {
    asm volatile("cp.async.cg.shared.global [%0], [%1], 16;" :: "r"(dst), "l"(src));
}
__device__ __forceinline__ void cp_commit() {
    asm volatile("cp.async.commit_group;");
}
__device__ __forceinline__ void cp_wait1() {
    asm volatile("cp.async.wait_group 1;");
}
__device__ __forceinline__ void cp_wait0() {
    asm volatile("cp.async.wait_group 0;");
}
__device__ __forceinline__ void ldmx4(uint32_t addr, uint32_t& r0, uint32_t& r1,
                                      uint32_t& r2, uint32_t& r3) {
    asm volatile("ldmatrix.sync.aligned.m8n8.x4.shared.b16 {%0,%1,%2,%3}, [%4];"
                 : "=r"(r0), "=r"(r1), "=r"(r2), "=r"(r3) : "r"(addr));
}
__device__ __forceinline__ void ldmx4t(uint32_t addr, uint32_t& r0, uint32_t& r1,
                                       uint32_t& r2, uint32_t& r3) {
    asm volatile("ldmatrix.sync.aligned.m8n8.x4.trans.shared.b16 {%0,%1,%2,%3}, [%4];"
                 : "=r"(r0), "=r"(r1), "=r"(r2), "=r"(r3) : "r"(addr));
}
__device__ __forceinline__ void mma_f16(float* c, const uint32_t* a, const uint32_t* b) {
    asm volatile("mma.sync.aligned.m16n8k16.row.col.f32.f16.f16.f32 "
                 "{%0,%1,%2,%3}, {%4,%5,%6,%7}, {%8,%9}, {%0,%1,%2,%3};"
                 : "+f"(c[0]), "+f"(c[1]), "+f"(c[2]), "+f"(c[3])
                 : "r"(a[0]), "r"(a[1]), "r"(a[2]), "r"(a[3]), "r"(b[0]), "r"(b[1]));
}
__device__ __forceinline__ uint32_t h2_bits(__half2 v) {
    return *reinterpret_cast<uint32_t*>(&v);
}
__device__ __forceinline__ uint32_t pack_h2(float a, float b) {
    return h2_bits(__floats2half2_rn(a, b));
}

// ---------------------------------------------------------------------------
// Weight convert: W fp32 -> fp16 plane, 16 elems/iter (MLP=4)
// ---------------------------------------------------------------------------
__global__ __launch_bounds__(256) void wconv_kernel(const float* __restrict__ W,
                                                    __half* __restrict__ out,
                                                    int n16)   // n/16
{
    const float4* W4 = reinterpret_cast<const float4*>(W);
    uint4* O4 = reinterpret_cast<uint4*>(out);
    for (int i = blockIdx.x * blockDim.x + threadIdx.x; i < n16; i += gridDim.x * blockDim.x) {
        float4 f0 = W4[4 * i];
        float4 f1 = W4[4 * i + 1];
        float4 f2 = W4[4 * i + 2];
        float4 f3 = W4[4 * i + 3];
        uint4 o0, o1;
        o0.x = pack_h2(f0.x, f0.y);
        o0.y = pack_h2(f0.z, f0.w);
        o0.z = pack_h2(f1.x, f1.y);
        o0.w = pack_h2(f1.z, f1.w);
        o1.x = pack_h2(f2.x, f2.y);
        o1.y = pack_h2(f2.z, f2.w);
        o1.z = pack_h2(f3.x, f3.y);
        o1.w = pack_h2(f3.z, f3.w);
        O4[2 * i]     = o0;
        O4[2 * i + 1] = o1;
    }
}

// ---------------------------------------------------------------------------
// Embedding + positional encoding; writes fp32 h AND fp16 activation plane
// ---------------------------------------------------------------------------
__global__ __launch_bounds__(256) void embed_kernel(const int* __restrict__ x,
                                                    const float* __restrict__ emb,
                                                    float* __restrict__ h,
                                                    __half* __restrict__ ah)
{
    int t = blockIdx.x;
    int s = t & (SS - 1);
    int tok = x[t];
    const float* e = emb + (size_t)tok * DD;
    const float negln = -9.210340371976184f;
    size_t base = (size_t)t * DD;
    for (int d0 = threadIdx.x * 2; d0 < DD; d0 += blockDim.x * 2) {
        float v[2];
        #pragma unroll
        for (int j = 0; j < 2; j++) {
            int d = d0 + j;
            int i2 = (d >> 1) * 2;
            float div = expf((float)i2 * (negln / (float)DD));
            float ang = (float)s * div;
            float pe = (d & 1) ? cosf(ang) : sinf(ang);
            v[j] = e[d] * 32.0f + pe;
        }
        h[base + d0] = v[0];
        h[base + d0 + 1] = v[1];
        *reinterpret_cast<uint32_t*>(ah + base + d0) = pack_h2(v[0], v[1]);
    }
}

// ---------------------------------------------------------------------------
// fp16 GEMM via mma.sync (R14 config, unchanged): 3-stage pipeline, 2 CTAs/SM.
// ---------------------------------------------------------------------------
__device__ __forceinline__ void stage_loadA(uint32_t sdst, const __half* A,
                                            int rowBase, int K, int k0, int tid)
{
    #pragma unroll
    for (int i = 0; i < 4; i++) {
        int idx = tid + i * 256;
        int r  = idx >> 3;
        int ch = idx & 7;
        uint32_t so = (uint32_t)r * AROWB + (uint32_t)ch * 16;
        cp_async16(sdst + so, A + (size_t)(rowBase + r) * K + k0 + ch * 8);
    }
}

__device__ __forceinline__ void stage_loadB(uint32_t sdst, const __half* Bw,
                                            int Nw, int colW, int k0, int tid)
{
    #pragma unroll
    for (int i = 0; i < 4; i++) {
        int idx = tid + i * 256;
        int r  = idx >> 4;
        int ch = idx & 15;
        uint32_t so = (uint32_t)r * BROWB + (uint32_t)ch * 16;
        cp_async16(sdst + so, Bw + (size_t)(k0 + r) * Nw + colW + ch * 8);
    }
}

template<int ACT, int OUTH>
__global__ __launch_bounds__(256, 2) void gemm_mma(const __half* __restrict__ A,
                                                   const __half* __restrict__ W0,
                                                   const __half* __restrict__ W1p,
                                                   const __half* __restrict__ W2p,
                                                   const float* __restrict__ bias,
                                                   float* __restrict__ C,
                                                   __half* __restrict__ Ch,
                                                   int M, int Nw, int K, int ldC)
{
    extern __shared__ char smem[];
    const uint32_t sb = smem_u32(smem);
    const int tid  = threadIdx.x;
    const int wid  = tid >> 5;
    const int lane = tid & 31;
    const int rowBase = blockIdx.x * BM;

    const __half* Bw = W0;
    int colW;
    if (W1p) {
        int wsel = blockIdx.y >> 3;
        if (wsel == 1)      Bw = W1p;
        else if (wsel == 2) Bw = W2p;
        colW = (blockIdx.y & 7) * BN;
    } else {
        colW = blockIdx.y * BN;
    }
    const int colC = blockIdx.y * BN;

    const int m0 = (wid >> 2) * 64;
    const int n0 = (wid & 3) * 32;
    const int g  = lane >> 3;
    const int lr = lane & 7;

    float acc[4][4][4];
    #pragma unroll
    for (int mt = 0; mt < 4; mt++)
        #pragma unroll
        for (int nt = 0; nt < 4; nt++)
            #pragma unroll
            for (int e = 0; e < 4; e++) acc[mt][nt][e] = 0.0f;

    const int KT = K / BK;

    stage_loadA(sb,        A,  rowBase, K, 0,  tid);
    stage_loadB(sb + ASTG, Bw, Nw, colW, 0,  tid);
    cp_commit();
    stage_loadA(sb + STG,        A,  rowBase, K, BK, tid);
    stage_loadB(sb + STG + ASTG, Bw, Nw, colW, BK, tid);
    cp_commit();

    int b0 = 0, b1 = 1, b2 = 2;

    for (int it = 0; it < KT; it++) {
        cp_wait1();
        __syncthreads();
        if (it + 2 < KT) {
            uint32_t d = sb + (uint32_t)b2 * STG;
            stage_loadA(d,        A,  rowBase, K, (it + 2) * BK, tid);
            stage_loadB(d + ASTG, Bw, Nw, colW, (it + 2) * BK, tid);
        }
        cp_commit();

        const uint32_t aB = sb + (uint32_t)b0 * STG;
        const uint32_t bB = aB + ASTG;
        #pragma unroll
        for (int ks = 0; ks < 4; ks++) {
            uint32_t Af[4][4];
            #pragma unroll
            for (int mt = 0; mt < 4; mt++) {
                int r  = m0 + mt * 16 + (g & 1) * 8 + lr;
                int ch = ks * 2 + (g >> 1);
                uint32_t ad = aB + (uint32_t)r * AROWB + (uint32_t)ch * 16;
                ldmx4(ad, Af[mt][0], Af[mt][1], Af[mt][2], Af[mt][3]);
            }
            uint32_t Bf[4][2];
            #pragma unroll
            for (int p = 0; p < 2; p++) {
                int kr = ks * 16 + (lane & 15);
                int nc = n0 + p * 16 + (lane >> 4) * 8;
                uint32_t bd = bB + (uint32_t)kr * BROWB + (uint32_t)nc * 2;
                ldmx4t(bd, Bf[2*p][0], Bf[2*p][1], Bf[2*p+1][0], Bf[2*p+1][1]);
            }
            #pragma unroll
            for (int mt = 0; mt < 4; mt++)
                #pragma unroll
                for (int nt = 0; nt < 4; nt++)
                    mma_f16(acc[mt][nt], Af[mt], Bf[nt]);
        }

        int t0 = b0; b0 = b1; b1 = b2; b2 = t0;
    }

    const int crow = lane >> 2;
    const int ccol = (lane & 3) * 2;
    #pragma unroll
    for (int mt = 0; mt < 4; mt++) {
        #pragma unroll
        for (int nt = 0; nt < 4; nt++) {
            int col = colC + n0 + nt * 8 + ccol;
            float bv0 = 0.0f, bv1 = 0.0f;
            if (bias) { bv0 = __ldg(bias + col); bv1 = __ldg(bias + col + 1); }
            #pragma unroll
            for (int half = 0; half < 2; half++) {
                int row = rowBase + m0 + mt * 16 + crow + half * 8;
                float v0 = acc[mt][nt][half * 2 + 0] + bv0;
                float v1 = acc[mt][nt][half * 2 + 1] + bv1;
                if (ACT == 1) {
                    v0 = 0.5f * v0 * (1.0f + erff(v0 * 0.7071067811865476f));
                    v1 = 0.5f * v1 * (1.0f + erff(v1 * 0.7071067811865476f));
                }
                if (OUTH) {
                    *reinterpret_cast<uint32_t*>(Ch + (size_t)row * ldC + col) = pack_h2(v0, v1);
                } else {
                    *reinterpret_cast<float2*>(&C[(size_t)row * ldC + col]) = make_float2(v0, v1);
                }
            }
        }
    }
}

// ---------------------------------------------------------------------------
// Tensor-core flash attention on fp16 qkv [NT, 3072]; emits fp16 ctx plane.
// Block = (b, h, 128 q-rows), 8 warps x 16-row tiles; 64-key K-tiles.
// S = Q@K^T via ldmx4 [n][k] operand; P@V via ldmx4t [k][n] operand.
// ---------------------------------------------------------------------------
__global__ __launch_bounds__(256) void attn_kernel(const __half* __restrict__ QKV,
                                                   const int* __restrict__ x,
                                                   __half* __restrict__ Oh)
{
    __shared__ char smem[4 * TTILE + 256];
    const uint32_t qB = smem_u32(smem);            // 128 rows: 2*TTILE
    const uint32_t kB = qB + 2 * TTILE;
    const uint32_t vB = qB + 3 * TTILE;
    int* validS = reinterpret_cast<int*>(smem + 4 * TTILE);

    const int tid  = threadIdx.x;
    const int b    = blockIdx.x >> 4;
    const int hh   = blockIdx.x & 15;
    const int qt   = (int)gridDim.y - 1 - (int)blockIdx.y;   // heavy blocks first
    const int qbase = qt * 128;
    const int w    = tid >> 5;
    const int lane = tid & 31;
    const int g    = lane >> 3;
    const int lr   = lane & 7;
    const int q4   = lane & 3;

    // Load Q tile (128 rows x 64 fp16): 1024 chunks / 256 threads
    #pragma unroll
    for (int i = 0; i < 4; i++) {
        int idx = tid + i * 256;
        int r = idx >> 3, c = idx & 7;
        cp_async16(qB + (uint32_t)r * TROWB + (uint32_t)c * 16,
                   QKV + (size_t)(b * SS + qbase + r) * QKVW + hh * DKH + c * 8);
    }
    cp_commit();
    cp_wait0();
    __syncthreads();

    // Q fragments (A operand), 4 k16 chunks; warp w owns rows [16w, 16w+16)
    uint32_t aQ[4][4];
    #pragma unroll
    for (int ks = 0; ks < 4; ks++) {
        int r  = 16 * w + (g & 1) * 8 + lr;
        int ch = ks * 2 + (g >> 1);
        ldmx4(qB + (uint32_t)r * TROWB + (uint32_t)ch * 16,
              aQ[ks][0], aQ[ks][1], aQ[ks][2], aQ[ks][3]);
    }

    float o[8][4];
    #pragma unroll
    for (int dt = 0; dt < 8; dt++)
        #pragma unroll
        for (int e = 0; e < 4; e++) o[dt][e] = 0.0f;
    float m0 = -1e30f, m1 = -1e30f, l0 = 0.0f, l1 = 0.0f;

    const int r0 = qbase + 16 * w + (lane >> 2);   // this thread's rows (seq-local)
    const int r1 = r0 + 8;
    const int ntiles = 2 * qt + 2;                 // 64-key tiles covering causal span

    for (int kt = 0; kt < ntiles; kt++) {
        const int kbase = kt * 64;
        __syncthreads();   // close previous tile reads before overwriting K/V
        #pragma unroll
        for (int i = 0; i < 2; i++) {
            int idx = tid + i * 256;
            int r = idx >> 3, c = idx & 7;
            size_t gsrc = (size_t)(b * SS + kbase + r) * QKVW + hh * DKH + c * 8;
            cp_async16(kB + (uint32_t)r * TROWB + (uint32_t)c * 16, QKV + gsrc + 1024);
            cp_async16(vB + (uint32_t)r * TROWB + (uint32_t)c * 16, QKV + gsrc + 2048);
        }
        if (tid < 64) validS[tid] = (x[b * SS + kbase + tid] != 0);
        cp_commit();
        cp_wait0();
        __syncthreads();

        // --- S = Q @ K^T  (n = key, k = dk; K rows are [n][k] -> plain ldmx4)
        float s[8][4];
        #pragma unroll
        for (int nt = 0; nt < 8; nt++)
            #pragma unroll
            for (int e = 0; e < 4; e++) s[nt][e] = 0.0f;
        #pragma unroll
        for (int ks = 0; ks < 4; ks++) {
            uint32_t Bk[8][2];
            #pragma unroll
            for (int p = 0; p < 4; p++) {
                int r  = p * 16 + (g >> 1) * 8 + lr;
                int ch = ks * 2 + (g & 1);
                ldmx4(kB + (uint32_t)r * TROWB + (uint32_t)ch * 16,
                      Bk[2*p][0], Bk[2*p][1], Bk[2*p+1][0], Bk[2*p+1][1]);
            }
            #pragma unroll
            for (int nt = 0; nt < 8; nt++)
                mma_f16(s[nt], aQ[ks], Bk[nt]);
        }

        // --- scale + mask
        #pragma unroll
        for (int nt = 0; nt < 8; nt++) {
            #pragma unroll
            for (int e = 0; e < 4; e++) {
                int col = nt * 8 + q4 * 2 + (e & 1);
                int key = kbase + col;
                int row = (e < 2) ? r0 : r1;
                float v = s[nt][e] * 0.125f;
                if (key > row || !validS[col]) v = -1e30f;
                s[nt][e] = v;
            }
        }

        // --- row max (quad reduction)
        float mx0 = -1e30f, mx1 = -1e30f;
        #pragma unroll
        for (int nt = 0; nt < 8; nt++) {
            mx0 = fmaxf(mx0, fmaxf(s[nt][0], s[nt][1]));
            mx1 = fmaxf(mx1, fmaxf(s[nt][2], s[nt][3]));
        }
        mx0 = fmaxf(mx0, __shfl_xor_sync(0xffffffffu, mx0, 1));
        mx0 = fmaxf(mx0, __shfl_xor_sync(0xffffffffu, mx0, 2));
        mx1 = fmaxf(mx1, __shfl_xor_sync(0xffffffffu, mx1, 1));
        mx1 = fmaxf(mx1, __shfl_xor_sync(0xffffffffu, mx1, 2));

        float mn0 = fmaxf(m0, mx0), mn1 = fmaxf(m1, mx1);
        float c0 = __expf(m0 - mn0), c1 = __expf(m1 - mn1);
        m0 = mn0; m1 = mn1;
        l0 *= c0; l1 *= c1;
        #pragma unroll
        for (int dt = 0; dt < 8; dt++) {
            o[dt][0] *= c0; o[dt][1] *= c0;
            o[dt][2] *= c1; o[dt][3] *= c1;
        }

        // --- P = exp(S - m), row sums
        float rs0 = 0.0f, rs1 = 0.0f;
        #pragma unroll
        for (int nt = 0; nt < 8; nt++) {
            s[nt][0] = __expf(s[nt][0] - m0);
            s[nt][1] = __expf(s[nt][1] - m0);
            s[nt][2] = __expf(s[nt][2] - m1);
            s[nt][3] = __expf(s[nt][3] - m1);
            rs0 += s[nt][0] + s[nt][1];
            rs1 += s[nt][2] + s[nt][3];
        }
        rs0 += __shfl_xor_sync(0xffffffffu, rs0, 1);
        rs0 += __shfl_xor_sync(0xffffffffu, rs0, 2);
        rs1 += __shfl_xor_sync(0xffffffffu, rs1, 1);
        rs1 += __shfl_xor_sync(0xffffffffu, rs1, 2);
        l0 += rs0; l1 += rs1;

        // --- O += P @ V  (k = key, n = d; V rows are [k][n] -> ldmx4t)
        #pragma unroll
        for (int kk = 0; kk < 4; kk++) {
            uint32_t aP[4];
            aP[0] = pack_h2(s[2*kk][0],   s[2*kk][1]);
            aP[1] = pack_h2(s[2*kk][2],   s[2*kk][3]);
            aP[2] = pack_h2(s[2*kk+1][0], s[2*kk+1][1]);
            aP[3] = pack_h2(s[2*kk+1][2], s[2*kk+1][3]);
            uint32_t Bv[8][2];
            #pragma unroll
            for (int p = 0; p < 4; p++) {
                int kr = kk * 16 + (lane & 15);
                int nc = p * 16 + (lane >> 4) * 8;
                ldmx4t(vB + (uint32_t)kr * TROWB + (uint32_t)nc * 2,
                       Bv[2*p][0], Bv[2*p][1], Bv[2*p+1][0], Bv[2*p+1][1]);
            }
            #pragma unroll
            for (int dt = 0; dt < 8; dt++)
                mma_f16(o[dt], aP, Bv[dt]);
        }
    }

    // --- finalize: O /= l, write fp16 ctx plane
    float inv0 = 1.0f / l0, inv1 = 1.0f / l1;
    size_t ob0 = (size_t)(b * SS + r0) * DD + hh * DKH;
    size_t ob1 = (size_t)(b * SS + r1) * DD + hh * DKH;
    #pragma unroll
    for (int dt = 0; dt < 8; dt++) {
        int col = dt * 8 + q4 * 2;
        *reinterpret_cast<uint32_t*>(Oh + ob0 + col) = pack_h2(o[dt][0] * inv0, o[dt][1] * inv0);
        *reinterpret_cast<uint32_t*>(Oh + ob1 + col) = pack_h2(o[dt][2] * inv1, o[dt][3] * inv1);
    }
}

// ---------------------------------------------------------------------------
// Residual add + LayerNorm (in place on h); also emits fp16 activation plane
// float4-vectorized: thread owns 4 contiguous elems.
// ---------------------------------------------------------------------------
__device__ __forceinline__ float block_sum(float v, float* red)
{
    #pragma unroll
    for (int o = 16; o > 0; o >>= 1) v += __shfl_xor_sync(0xffffffffu, v, o);
    int w = threadIdx.x >> 5;
    if ((threadIdx.x & 31) == 0) red[w] = v;
    __syncthreads();
    if (threadIdx.x < 32) {
        float t = (threadIdx.x < 8) ? red[threadIdx.x] : 0.0f;
        #pragma unroll
        for (int o = 4; o > 0; o >>= 1) t += __shfl_xor_sync(0xffffffffu, t, o);
        if (threadIdx.x == 0) red[0] = t;
    }
    __syncthreads();
    float r = red[0];
    __syncthreads();
    return r;
}

__global__ __launch_bounds__(256) void add_ln_kernel(float* __restrict__ h,
                                                     const float* __restrict__ r,
                                                     const float* __restrict__ g,
                                                     const float* __restrict__ bta,
                                                     __half* __restrict__ ah)
{
    __shared__ float red[32];
    const int t = blockIdx.x;
    const int tid = threadIdx.x;
    const int d0 = tid * 4;
    size_t base = (size_t)t * DD;

    float4 hv = *reinterpret_cast<const float4*>(h + base + d0);
    float4 rv = *reinterpret_cast<const float4*>(r + base + d0);
    float v0 = hv.x + rv.x, v1 = hv.y + rv.y, v2 = hv.z + rv.z, v3 = hv.w + rv.w;

    float tot = block_sum(v0 + v1 + v2 + v3, red);
    float mu = tot * (1.0f / (float)DD);
    float dv0 = v0 - mu, dv1 = v1 - mu, dv2 = v2 - mu, dv3 = v3 - mu;
    float var = block_sum(dv0*dv0 + dv1*dv1 + dv2*dv2 + dv3*dv3, red) * (1.0f / (float)DD);
    float rs = rsqrtf(var + 1e-5f);

    float4 gv = *reinterpret_cast<const float4*>(g + d0);
    float4 bv = *reinterpret_cast<const float4*>(bta + d0);
    float o0 = dv0 * rs * gv.x + bv.x;
    float o1 = dv1 * rs * gv.y + bv.y;
    float o2 = dv2 * rs * gv.z + bv.z;
    float o3 = dv3 * rs * gv.w + bv.w;

    *reinterpret_cast<float4*>(h + base + d0) = make_float4(o0, o1, o2, o3);
    uint2 pw;
    pw.x = pack_h2(o0, o1);
    pw.y = pack_h2(o2, o3);
    *reinterpret_cast<uint2*>(ah + base + d0) = pw;
}

// ---------------------------------------------------------------------------
// Launch
// ---------------------------------------------------------------------------
extern "C" void kernel_launch(void* const* d_in, const int* in_sizes, int n_in,
                              void* d_out, int out_size)
{
    const int*   x    = (const int*)  d_in[0];
    const float* emb  = (const float*)d_in[1];
    const float* Wq   = (const float*)d_in[2];
    const float* Wk   = (const float*)d_in[3];
    const float* Wv   = (const float*)d_in[4];
    const float* Wo   = (const float*)d_in[5];
    const float* bo   = (const float*)d_in[6];
    const float* ln1g = (const float*)d_in[7];
    const float* ln1b = (const float*)d_in[8];
    const float* ln2g = (const float*)d_in[9];
    const float* ln2b = (const float*)d_in[10];
    const float* W1   = (const float*)d_in[11];
    const float* b1   = (const float*)d_in[12];
    const float* W2   = (const float*)d_in[13];
    const float* b2   = (const float*)d_in[14];
    const float* Wout = (const float*)d_in[15];
    const float* bout = (const float*)d_in[16];
    float* out = (float*)d_out;

    void* p;
    cudaGetSymbolAddress(&p, g_h);   float* h   = (float*)p;
    cudaGetSymbolAddress(&p, g_tmp); float* tmp = (float*)p;
    cudaGetSymbolAddress(&p, g_qh);  __half* qh = (__half*)p;
    cudaGetSymbolAddress(&p, g_ah);  __half* ah = (__half*)p;
    cudaGetSymbolAddress(&p, g_fh);  __half* fh = (__half*)p;
    cudaGetSymbolAddress(&p, g_wh);  __half* wh = (__half*)p;

    cudaFuncSetAttribute(gemm_mma<0,0>, cudaFuncAttributeMaxDynamicSharedMemorySize, GEMM_SMEM);
    cudaFuncSetAttribute(gemm_mma<0,1>, cudaFuncAttributeMaxDynamicSharedMemorySize, GEMM_SMEM);
    cudaFuncSetAttribute(gemm_mma<1,1>, cudaFuncAttributeMaxDynamicSharedMemorySize, GEMM_SMEM);

    // Convert all weights to fp16 planes (streaming, once per launch)
    wconv_kernel<<<1024, 256>>>(Wq,   wh + OFF_WQ,   LL*DD*DD/16);
    wconv_kernel<<<1024, 256>>>(Wk,   wh + OFF_WK,   LL*DD*DD/16);
    wconv_kernel<<<1024, 256>>>(Wv,   wh + OFF_WV,   LL*DD*DD/16);
    wconv_kernel<<<1024, 256>>>(Wo,   wh + OFF_WO,   LL*DD*DD/16);
    wconv_kernel<<<2048, 256>>>(W1,   wh + OFF_W1,   LL*DD*FF/16);
    wconv_kernel<<<2048, 256>>>(W2,   wh + OFF_W2,   LL*DD*FF/16);
    wconv_kernel<<<2048, 256>>>(Wout, wh + OFF_WOUT, DD*VV/16);

    embed_kernel<<<NT, 256>>>(x, emb, h, ah);

    const dim3 gQKV(NT/BM, QKVW/BN);  // 32 x 24 (fused q|k|v)
    const dim3 gD(NT/BM, DD/BN);      // 32 x 8
    const dim3 gF(NT/BM, FF/BN);      // 32 x 32
    const dim3 gV(NT/BM, VV/BN);      // 32 x 250

    for (int l = 0; l < LL; l++) {
        const size_t oD = (size_t)l * DD * DD;
        const size_t oF = (size_t)l * DD * FF;

        // Fused QKV projection -> fp16 qh buffer
        gemm_mma<0,1><<<gQKV, 256, GEMM_SMEM>>>(ah,
            wh + OFF_WQ + oD, wh + OFF_WK + oD, wh + OFF_WV + oD,
            nullptr, nullptr, qh, NT, DD, DD, QKVW);

        attn_kernel<<<dim3(BB * HH, SS / 128), 256>>>(qh, x, ah);   // ctx -> fp16 plane

        gemm_mma<0,0><<<gD, 256, GEMM_SMEM>>>(ah,
            wh + OFF_WO + oD, nullptr, nullptr,
            bo + l * DD, tmp, nullptr, NT, DD, DD, DD);
        add_ln_kernel<<<NT, 256>>>(h, tmp, ln1g + l * DD, ln1b + l * DD, ah);

        gemm_mma<1,1><<<gF, 256, GEMM_SMEM>>>(ah,
            wh + OFF_W1 + oF, nullptr, nullptr,
            b1 + l * FF, nullptr, fh, NT, FF, DD, FF);
        gemm_mma<0,0><<<gD, 256, GEMM_SMEM>>>(fh,
            wh + OFF_W2 + oF, nullptr, nullptr,
            b2 + l * DD, tmp, nullptr, NT, DD, FF, DD);
        add_ln_kernel<<<NT, 256>>>(h, tmp, ln2g + l * DD, ln2b + l * DD, ah);
    }

    gemm_mma<0,0><<<gV, 256, GEMM_SMEM>>>(ah,
        wh + OFF_WOUT, nullptr, nullptr,
        bout, out, nullptr, NT, VV, DD, VV);
}

// round 17
// speedup vs baseline: 1.0224x; 1.0224x over previous
#include <cuda_runtime.h>
#include <cuda_fp16.h>
#include <cstdint>
#include <cmath>

// Problem constants
#define BB   4
#define SS   1024
#define DD   1024
#define HH   16
#define DKH  64
#define LL   4
#define FF   4096
#define VV   32000
#define NT   (BB*SS)   // 4096 tokens
#define QKVW 3072      // packed q|k|v width

// GEMM tile config: CTA 128x128, warp 64x32 (2x4 warps), BK=64, 3-stage, 2 CTAs/SM
#define BM 128
#define BN 128
#define BK 64
#define AROWB 144                  // A smem row: 128B data + 16B pad
#define ASTG (BM*AROWB)            // one 128xBK fp16 matrix: 18432 B
#define BROWB 272                  // B smem row: 256B data + 16B pad
#define BSTG (64*BROWB)            // one 64x128 fp16 plane per stage: 17408 B
#define STG (ASTG + BSTG)          // 35840 B per stage
#define GEMM_SMEM (3*STG)          // 107520 B  (2 CTAs/SM: 215040 <= ~227KB)

// Attention smem
#define TROWB 144                  // 64 fp16 = 128B + 16B pad
#define TTILE (64*TROWB)           // 9216 B

// fp16 weight plane offsets (elements)
#define OFF_WQ   0
#define OFF_WK   (4*DD*DD)
#define OFF_WV   (8*DD*DD)
#define OFF_WO   (12*DD*DD)
#define OFF_W1   (16*DD*DD)
#define OFF_W2   (OFF_W1 + LL*DD*FF)
#define OFF_WOUT (OFF_W2 + LL*DD*FF)
#define WTOT     (OFF_WOUT + (size_t)DD*VV)   // 83,099,648 elems

// ---------------------------------------------------------------------------
// Scratch (device globals — no runtime allocation allowed)
// ---------------------------------------------------------------------------
__device__ float g_h  [NT*(size_t)DD];
__device__ float g_tmp[NT*(size_t)DD];
__device__ __half g_qh [NT*(size_t)QKVW];
__device__ __half g_ah [NT*(size_t)DD];
__device__ __half g_fh [NT*(size_t)FF];
__device__ __half g_wh [WTOT];

// ---------------------------------------------------------------------------
// PTX helpers
// ---------------------------------------------------------------------------
__device__ __forceinline__ uint32_t smem_u32(const void* p) {
    uint32_t a;
    asm("{ .reg .u64 t; cvta.to.shared.u64 t, %1; cvt.u32.u64 %0, t; }" : "=r"(a) : "l"(p));
    return a;
}
__device__ __forceinline__ void cp_async16(uint32_t dst, const void* src) {
    asm volatile("cp.async.cg.shared.global [%0], [%1], 16;" :: "r"(dst), "l"(src));
}
__device__ __forceinline__ void cp_commit() {
    asm volatile("cp.async.commit_group;");
}
__device__ __forceinline__ void cp_wait1() {
    asm volatile("cp.async.wait_group 1;");
}
__device__ __forceinline__ void cp_wait0() {
    asm volatile("cp.async.wait_group 0;");
}
__device__ __forceinline__ void ldmx4(uint32_t addr, uint32_t& r0, uint32_t& r1,
                                      uint32_t& r2, uint32_t& r3) {
    asm volatile("ldmatrix.sync.aligned.m8n8.x4.shared.b16 {%0,%1,%2,%3}, [%4];"
                 : "=r"(r0), "=r"(r1), "=r"(r2), "=r"(r3) : "r"(addr));
}
__device__ __forceinline__ void ldmx4t(uint32_t addr, uint32_t& r0, uint32_t& r1,
                                       uint32_t& r2, uint32_t& r3) {
    asm volatile("ldmatrix.sync.aligned.m8n8.x4.trans.shared.b16 {%0,%1,%2,%3}, [%4];"
                 : "=r"(r0), "=r"(r1), "=r"(r2), "=r"(r3) : "r"(addr));
}
__device__ __forceinline__ void mma_f16(float* c, const uint32_t* a, const uint32_t* b) {
    asm volatile("mma.sync.aligned.m16n8k16.row.col.f32.f16.f16.f32 "
                 "{%0,%1,%2,%3}, {%4,%5,%6,%7}, {%8,%9}, {%0,%1,%2,%3};"
                 : "+f"(c[0]), "+f"(c[1]), "+f"(c[2]), "+f"(c[3])
                 : "r"(a[0]), "r"(a[1]), "r"(a[2]), "r"(a[3]), "r"(b[0]), "r"(b[1]));
}
__device__ __forceinline__ uint32_t h2_bits(__half2 v) {
    return *reinterpret_cast<uint32_t*>(&v);
}
__device__ __forceinline__ uint32_t pack_h2(float a, float b) {
    return h2_bits(__floats2half2_rn(a, b));
}

// ---------------------------------------------------------------------------
// Weight convert: W fp32 -> fp16 plane, 16 elems/iter (MLP=4)
// ---------------------------------------------------------------------------
__global__ __launch_bounds__(256) void wconv_kernel(const float* __restrict__ W,
                                                    __half* __restrict__ out,
                                                    int n16)   // n/16
{
    const float4* W4 = reinterpret_cast<const float4*>(W);
    uint4* O4 = reinterpret_cast<uint4*>(out);
    for (int i = blockIdx.x * blockDim.x + threadIdx.x; i < n16; i += gridDim.x * blockDim.x) {
        float4 f0 = W4[4 * i];
        float4 f1 = W4[4 * i + 1];
        float4 f2 = W4[4 * i + 2];
        float4 f3 = W4[4 * i + 3];
        uint4 o0, o1;
        o0.x = pack_h2(f0.x, f0.y);
        o0.y = pack_h2(f0.z, f0.w);
        o0.z = pack_h2(f1.x, f1.y);
        o0.w = pack_h2(f1.z, f1.w);
        o1.x = pack_h2(f2.x, f2.y);
        o1.y = pack_h2(f2.z, f2.w);
        o1.z = pack_h2(f3.x, f3.y);
        o1.w = pack_h2(f3.z, f3.w);
        O4[2 * i]     = o0;
        O4[2 * i + 1] = o1;
    }
}

// ---------------------------------------------------------------------------
// Embedding + positional encoding; writes fp32 h AND fp16 activation plane
// ---------------------------------------------------------------------------
__global__ __launch_bounds__(256) void embed_kernel(const int* __restrict__ x,
                                                    const float* __restrict__ emb,
                                                    float* __restrict__ h,
                                                    __half* __restrict__ ah)
{
    int t = blockIdx.x;
    int s = t & (SS - 1);
    int tok = x[t];
    const float* e = emb + (size_t)tok * DD;
    const float negln = -9.210340371976184f;
    size_t base = (size_t)t * DD;
    for (int d0 = threadIdx.x * 2; d0 < DD; d0 += blockDim.x * 2) {
        float v[2];
        #pragma unroll
        for (int j = 0; j < 2; j++) {
            int d = d0 + j;
            int i2 = (d >> 1) * 2;
            float div = expf((float)i2 * (negln / (float)DD));
            float ang = (float)s * div;
            float pe = (d & 1) ? cosf(ang) : sinf(ang);
            v[j] = e[d] * 32.0f + pe;
        }
        h[base + d0] = v[0];
        h[base + d0 + 1] = v[1];
        *reinterpret_cast<uint32_t*>(ah + base + d0) = pack_h2(v[0], v[1]);
    }
}

// ---------------------------------------------------------------------------
// fp16 GEMM via mma.sync: 3-stage cp.async pipeline, 2 CTAs/SM,
// B fragments register double-buffered across ks steps.
// ---------------------------------------------------------------------------
__device__ __forceinline__ void stage_loadA(uint32_t sdst, const __half* A,
                                            int rowBase, int K, int k0, int tid)
{
    #pragma unroll
    for (int i = 0; i < 4; i++) {
        int idx = tid + i * 256;
        int r  = idx >> 3;
        int ch = idx & 7;
        uint32_t so = (uint32_t)r * AROWB + (uint32_t)ch * 16;
        cp_async16(sdst + so, A + (size_t)(rowBase + r) * K + k0 + ch * 8);
    }
}

__device__ __forceinline__ void stage_loadB(uint32_t sdst, const __half* Bw,
                                            int Nw, int colW, int k0, int tid)
{
    #pragma unroll
    for (int i = 0; i < 4; i++) {
        int idx = tid + i * 256;
        int r  = idx >> 4;
        int ch = idx & 15;
        uint32_t so = (uint32_t)r * BROWB + (uint32_t)ch * 16;
        cp_async16(sdst + so, Bw + (size_t)(k0 + r) * Nw + colW + ch * 8);
    }
}

template<int ACT, int OUTH>
__global__ __launch_bounds__(256, 2) void gemm_mma(const __half* __restrict__ A,
                                                   const __half* __restrict__ W0,
                                                   const __half* __restrict__ W1p,
                                                   const __half* __restrict__ W2p,
                                                   const float* __restrict__ bias,
                                                   float* __restrict__ C,
                                                   __half* __restrict__ Ch,
                                                   int M, int Nw, int K, int ldC)
{
    extern __shared__ char smem[];
    const uint32_t sb = smem_u32(smem);
    const int tid  = threadIdx.x;
    const int wid  = tid >> 5;
    const int lane = tid & 31;
    const int rowBase = blockIdx.x * BM;

    const __half* Bw = W0;
    int colW;
    if (W1p) {
        int wsel = blockIdx.y >> 3;
        if (wsel == 1)      Bw = W1p;
        else if (wsel == 2) Bw = W2p;
        colW = (blockIdx.y & 7) * BN;
    } else {
        colW = blockIdx.y * BN;
    }
    const int colC = blockIdx.y * BN;

    const int m0 = (wid >> 2) * 64;
    const int n0 = (wid & 3) * 32;
    const int g  = lane >> 3;
    const int lr = lane & 7;

    float acc[4][4][4];
    #pragma unroll
    for (int mt = 0; mt < 4; mt++)
        #pragma unroll
        for (int nt = 0; nt < 4; nt++)
            #pragma unroll
            for (int e = 0; e < 4; e++) acc[mt][nt][e] = 0.0f;

    const int KT = K / BK;

    stage_loadA(sb,        A,  rowBase, K, 0,  tid);
    stage_loadB(sb + ASTG, Bw, Nw, colW, 0,  tid);
    cp_commit();
    stage_loadA(sb + STG,        A,  rowBase, K, BK, tid);
    stage_loadB(sb + STG + ASTG, Bw, Nw, colW, BK, tid);
    cp_commit();

    int b0 = 0, b1 = 1, b2 = 2;
    const int bkr = lane & 15;          // B fragment k-row within 16
    const int bnc = n0 + (lane >> 4) * 8;

    for (int it = 0; it < KT; it++) {
        cp_wait1();
        __syncthreads();
        if (it + 2 < KT) {
            uint32_t d = sb + (uint32_t)b2 * STG;
            stage_loadA(d,        A,  rowBase, K, (it + 2) * BK, tid);
            stage_loadB(d + ASTG, Bw, Nw, colW, (it + 2) * BK, tid);
        }
        cp_commit();

        const uint32_t aB = sb + (uint32_t)b0 * STG;
        const uint32_t bB = aB + ASTG;

        // B fragments for ks=0 (double-buffered across ks)
        uint32_t Bf[2][4][2];
        {
            uint32_t bd0 = bB + (uint32_t)bkr * BROWB + (uint32_t)bnc * 2;
            ldmx4t(bd0,       Bf[0][0][0], Bf[0][0][1], Bf[0][1][0], Bf[0][1][1]);
            ldmx4t(bd0 + 32,  Bf[0][2][0], Bf[0][2][1], Bf[0][3][0], Bf[0][3][1]);
        }

        #pragma unroll
        for (int ks = 0; ks < 4; ks++) {
            const int cur = ks & 1;
            if (ks < 3) {
                const int nxt = cur ^ 1;
                uint32_t bd = bB + (uint32_t)((ks + 1) * 16 + bkr) * BROWB + (uint32_t)bnc * 2;
                ldmx4t(bd,      Bf[nxt][0][0], Bf[nxt][0][1], Bf[nxt][1][0], Bf[nxt][1][1]);
                ldmx4t(bd + 32, Bf[nxt][2][0], Bf[nxt][2][1], Bf[nxt][3][0], Bf[nxt][3][1]);
            }
            uint32_t Af[4][4];
            #pragma unroll
            for (int mt = 0; mt < 4; mt++) {
                int r  = m0 + mt * 16 + (g & 1) * 8 + lr;
                int ch = ks * 2 + (g >> 1);
                uint32_t ad = aB + (uint32_t)r * AROWB + (uint32_t)ch * 16;
                ldmx4(ad, Af[mt][0], Af[mt][1], Af[mt][2], Af[mt][3]);
            }
            #pragma unroll
            for (int mt = 0; mt < 4; mt++)
                #pragma unroll
                for (int nt = 0; nt < 4; nt++)
                    mma_f16(acc[mt][nt], Af[mt], Bf[cur][nt]);
        }

        int t0 = b0; b0 = b1; b1 = b2; b2 = t0;
    }

    const int crow = lane >> 2;
    const int ccol = (lane & 3) * 2;
    #pragma unroll
    for (int mt = 0; mt < 4; mt++) {
        #pragma unroll
        for (int nt = 0; nt < 4; nt++) {
            int col = colC + n0 + nt * 8 + ccol;
            float bv0 = 0.0f, bv1 = 0.0f;
            if (bias) { bv0 = __ldg(bias + col); bv1 = __ldg(bias + col + 1); }
            #pragma unroll
            for (int half = 0; half < 2; half++) {
                int row = rowBase + m0 + mt * 16 + crow + half * 8;
                float v0 = acc[mt][nt][half * 2 + 0] + bv0;
                float v1 = acc[mt][nt][half * 2 + 1] + bv1;
                if (ACT == 1) {
                    v0 = 0.5f * v0 * (1.0f + erff(v0 * 0.7071067811865476f));
                    v1 = 0.5f * v1 * (1.0f + erff(v1 * 0.7071067811865476f));
                }
                if (OUTH) {
                    *reinterpret_cast<uint32_t*>(Ch + (size_t)row * ldC + col) = pack_h2(v0, v1);
                } else {
                    *reinterpret_cast<float2*>(&C[(size_t)row * ldC + col]) = make_float2(v0, v1);
                }
            }
        }
    }
}

// ---------------------------------------------------------------------------
// Tensor-core flash attention (R15 config: 64 q-rows, 128 threads).
// ---------------------------------------------------------------------------
__global__ __launch_bounds__(128) void attn_kernel(const __half* __restrict__ QKV,
                                                   const int* __restrict__ x,
                                                   __half* __restrict__ Oh)
{
    __shared__ char smem[3 * TTILE + 256];
    const uint32_t qB = smem_u32(smem);
    const uint32_t kB = qB + TTILE;
    const uint32_t vB = qB + 2 * TTILE;
    int* validS = reinterpret_cast<int*>(smem + 3 * TTILE);

    const int tid  = threadIdx.x;
    const int b    = blockIdx.x >> 4;
    const int hh   = blockIdx.x & 15;
    const int qt   = (int)gridDim.y - 1 - (int)blockIdx.y;
    const int qbase = qt * 64;
    const int w    = tid >> 5;
    const int lane = tid & 31;
    const int g    = lane >> 3;
    const int lr   = lane & 7;
    const int q4   = lane & 3;

    #pragma unroll
    for (int i = 0; i < 4; i++) {
        int idx = tid + i * 128;
        int r = idx >> 3, c = idx & 7;
        cp_async16(qB + (uint32_t)r * TROWB + (uint32_t)c * 16,
                   QKV + (size_t)(b * SS + qbase + r) * QKVW + hh * DKH + c * 8);
    }
    cp_commit();
    cp_wait0();
    __syncthreads();

    uint32_t aQ[4][4];
    #pragma unroll
    for (int ks = 0; ks < 4; ks++) {
        int r  = 16 * w + (g & 1) * 8 + lr;
        int ch = ks * 2 + (g >> 1);
        ldmx4(qB + (uint32_t)r * TROWB + (uint32_t)ch * 16,
              aQ[ks][0], aQ[ks][1], aQ[ks][2], aQ[ks][3]);
    }

    float o[8][4];
    #pragma unroll
    for (int dt = 0; dt < 8; dt++)
        #pragma unroll
        for (int e = 0; e < 4; e++) o[dt][e] = 0.0f;
    float m0 = -1e30f, m1 = -1e30f, l0 = 0.0f, l1 = 0.0f;

    const int r0 = qbase + 16 * w + (lane >> 2);
    const int r1 = r0 + 8;

    for (int kt = 0; kt <= qt; kt++) {
        const int kbase = kt * 64;
        __syncthreads();
        #pragma unroll
        for (int i = 0; i < 4; i++) {
            int idx = tid + i * 128;
            int r = idx >> 3, c = idx & 7;
            size_t gsrc = (size_t)(b * SS + kbase + r) * QKVW + hh * DKH + c * 8;
            cp_async16(kB + (uint32_t)r * TROWB + (uint32_t)c * 16, QKV + gsrc + 1024);
            cp_async16(vB + (uint32_t)r * TROWB + (uint32_t)c * 16, QKV + gsrc + 2048);
        }
        if (tid < 64) validS[tid] = (x[b * SS + kbase + tid] != 0);
        cp_commit();
        cp_wait0();
        __syncthreads();

        float s[8][4];
        #pragma unroll
        for (int nt = 0; nt < 8; nt++)
            #pragma unroll
            for (int e = 0; e < 4; e++) s[nt][e] = 0.0f;
        #pragma unroll
        for (int ks = 0; ks < 4; ks++) {
            uint32_t Bk[8][2];
            #pragma unroll
            for (int p = 0; p < 4; p++) {
                int r  = p * 16 + (g >> 1) * 8 + lr;
                int ch = ks * 2 + (g & 1);
                ldmx4(kB + (uint32_t)r * TROWB + (uint32_t)ch * 16,
                      Bk[2*p][0], Bk[2*p][1], Bk[2*p+1][0], Bk[2*p+1][1]);
            }
            #pragma unroll
            for (int nt = 0; nt < 8; nt++)
                mma_f16(s[nt], aQ[ks], Bk[nt]);
        }

        #pragma unroll
        for (int nt = 0; nt < 8; nt++) {
            #pragma unroll
            for (int e = 0; e < 4; e++) {
                int col = nt * 8 + q4 * 2 + (e & 1);
                int key = kbase + col;
                int row = (e < 2) ? r0 : r1;
                float v = s[nt][e] * 0.125f;
                if (key > row || !validS[col]) v = -1e30f;
                s[nt][e] = v;
            }
        }

        float mx0 = -1e30f, mx1 = -1e30f;
        #pragma unroll
        for (int nt = 0; nt < 8; nt++) {
            mx0 = fmaxf(mx0, fmaxf(s[nt][0], s[nt][1]));
            mx1 = fmaxf(mx1, fmaxf(s[nt][2], s[nt][3]));
        }
        mx0 = fmaxf(mx0, __shfl_xor_sync(0xffffffffu, mx0, 1));
        mx0 = fmaxf(mx0, __shfl_xor_sync(0xffffffffu, mx0, 2));
        mx1 = fmaxf(mx1, __shfl_xor_sync(0xffffffffu, mx1, 1));
        mx1 = fmaxf(mx1, __shfl_xor_sync(0xffffffffu, mx1, 2));

        float mn0 = fmaxf(m0, mx0), mn1 = fmaxf(m1, mx1);
        float c0 = __expf(m0 - mn0), c1 = __expf(m1 - mn1);
        m0 = mn0; m1 = mn1;
        l0 *= c0; l1 *= c1;
        #pragma unroll
        for (int dt = 0; dt < 8; dt++) {
            o[dt][0] *= c0; o[dt][1] *= c0;
            o[dt][2] *= c1; o[dt][3] *= c1;
        }

        float rs0 = 0.0f, rs1 = 0.0f;
        #pragma unroll
        for (int nt = 0; nt < 8; nt++) {
            s[nt][0] = __expf(s[nt][0] - m0);
            s[nt][1] = __expf(s[nt][1] - m0);
            s[nt][2] = __expf(s[nt][2] - m1);
            s[nt][3] = __expf(s[nt][3] - m1);
            rs0 += s[nt][0] + s[nt][1];
            rs1 += s[nt][2] + s[nt][3];
        }
        rs0 += __shfl_xor_sync(0xffffffffu, rs0, 1);
        rs0 += __shfl_xor_sync(0xffffffffu, rs0, 2);
        rs1 += __shfl_xor_sync(0xffffffffu, rs1, 1);
        rs1 += __shfl_xor_sync(0xffffffffu, rs1, 2);
        l0 += rs0; l1 += rs1;

        #pragma unroll
        for (int kk = 0; kk < 4; kk++) {
            uint32_t aP[4];
            aP[0] = pack_h2(s[2*kk][0],   s[2*kk][1]);
            aP[1] = pack_h2(s[2*kk][2],   s[2*kk][3]);
            aP[2] = pack_h2(s[2*kk+1][0], s[2*kk+1][1]);
            aP[3] = pack_h2(s[2*kk+1][2], s[2*kk+1][3]);
            uint32_t Bv[8][2];
            #pragma unroll
            for (int p = 0; p < 4; p++) {
                int kr = kk * 16 + (lane & 15);
                int nc = p * 16 + (lane >> 4) * 8;
                ldmx4t(vB + (uint32_t)kr * TROWB + (uint32_t)nc * 2,
                       Bv[2*p][0], Bv[2*p][1], Bv[2*p+1][0], Bv[2*p+1][1]);
            }
            #pragma unroll
            for (int dt = 0; dt < 8; dt++)
                mma_f16(o[dt], aP, Bv[dt]);
        }
    }

    float inv0 = 1.0f / l0, inv1 = 1.0f / l1;
    size_t ob0 = (size_t)(b * SS + r0) * DD + hh * DKH;
    size_t ob1 = (size_t)(b * SS + r1) * DD + hh * DKH;
    #pragma unroll
    for (int dt = 0; dt < 8; dt++) {
        int col = dt * 8 + q4 * 2;
        *reinterpret_cast<uint32_t*>(Oh + ob0 + col) = pack_h2(o[dt][0] * inv0, o[dt][1] * inv0);
        *reinterpret_cast<uint32_t*>(Oh + ob1 + col) = pack_h2(o[dt][2] * inv1, o[dt][3] * inv1);
    }
}

// ---------------------------------------------------------------------------
// Residual add + LayerNorm (float4-vectorized; emits fp16 plane)
// ---------------------------------------------------------------------------
__device__ __forceinline__ float block_sum(float v, float* red)
{
    #pragma unroll
    for (int o = 16; o > 0; o >>= 1) v += __shfl_xor_sync(0xffffffffu, v, o);
    int w = threadIdx.x >> 5;
    if ((threadIdx.x & 31) == 0) red[w] = v;
    __syncthreads();
    if (threadIdx.x < 32) {
        float t = (threadIdx.x < 8) ? red[threadIdx.x] : 0.0f;
        #pragma unroll
        for (int o = 4; o > 0; o >>= 1) t += __shfl_xor_sync(0xffffffffu, t, o);
        if (threadIdx.x == 0) red[0] = t;
    }
    __syncthreads();
    float r = red[0];
    __syncthreads();
    return r;
}

__global__ __launch_bounds__(256) void add_ln_kernel(float* __restrict__ h,
                                                     const float* __restrict__ r,
                                                     const float* __restrict__ g,
                                                     const float* __restrict__ bta,
                                                     __half* __restrict__ ah)
{
    __shared__ float red[32];
    const int t = blockIdx.x;
    const int tid = threadIdx.x;
    const int d0 = tid * 4;
    size_t base = (size_t)t * DD;

    float4 hv = *reinterpret_cast<const float4*>(h + base + d0);
    float4 rv = *reinterpret_cast<const float4*>(r + base + d0);
    float v0 = hv.x + rv.x, v1 = hv.y + rv.y, v2 = hv.z + rv.z, v3 = hv.w + rv.w;

    float tot = block_sum(v0 + v1 + v2 + v3, red);
    float mu = tot * (1.0f / (float)DD);
    float dv0 = v0 - mu, dv1 = v1 - mu, dv2 = v2 - mu, dv3 = v3 - mu;
    float var = block_sum(dv0*dv0 + dv1*dv1 + dv2*dv2 + dv3*dv3, red) * (1.0f / (float)DD);
    float rs = rsqrtf(var + 1e-5f);

    float4 gv = *reinterpret_cast<const float4*>(g + d0);
    float4 bv = *reinterpret_cast<const float4*>(bta + d0);
    float o0 = dv0 * rs * gv.x + bv.x;
    float o1 = dv1 * rs * gv.y + bv.y;
    float o2 = dv2 * rs * gv.z + bv.z;
    float o3 = dv3 * rs * gv.w + bv.w;

    *reinterpret_cast<float4*>(h + base + d0) = make_float4(o0, o1, o2, o3);
    uint2 pw;
    pw.x = pack_h2(o0, o1);
    pw.y = pack_h2(o2, o3);
    *reinterpret_cast<uint2*>(ah + base + d0) = pw;
}

// ---------------------------------------------------------------------------
// Launch (ordered so the fused QKV GEMM is launch #6 for ncu -s 5 -c 1)
// ---------------------------------------------------------------------------
extern "C" void kernel_launch(void* const* d_in, const int* in_sizes, int n_in,
                              void* d_out, int out_size)
{
    const int*   x    = (const int*)  d_in[0];
    const float* emb  = (const float*)d_in[1];
    const float* Wq   = (const float*)d_in[2];
    const float* Wk   = (const float*)d_in[3];
    const float* Wv   = (const float*)d_in[4];
    const float* Wo   = (const float*)d_in[5];
    const float* bo   = (const float*)d_in[6];
    const float* ln1g = (const float*)d_in[7];
    const float* ln1b = (const float*)d_in[8];
    const float* ln2g = (const float*)d_in[9];
    const float* ln2b = (const float*)d_in[10];
    const float* W1   = (const float*)d_in[11];
    const float* b1   = (const float*)d_in[12];
    const float* W2   = (const float*)d_in[13];
    const float* b2   = (const float*)d_in[14];
    const float* Wout = (const float*)d_in[15];
    const float* bout = (const float*)d_in[16];
    float* out = (float*)d_out;

    void* p;
    cudaGetSymbolAddress(&p, g_h);   float* h   = (float*)p;
    cudaGetSymbolAddress(&p, g_tmp); float* tmp = (float*)p;
    cudaGetSymbolAddress(&p, g_qh);  __half* qh = (__half*)p;
    cudaGetSymbolAddress(&p, g_ah);  __half* ah = (__half*)p;
    cudaGetSymbolAddress(&p, g_fh);  __half* fh = (__half*)p;
    cudaGetSymbolAddress(&p, g_wh);  __half* wh = (__half*)p;

    cudaFuncSetAttribute(gemm_mma<0,0>, cudaFuncAttributeMaxDynamicSharedMemorySize, GEMM_SMEM);
    cudaFuncSetAttribute(gemm_mma<0,1>, cudaFuncAttributeMaxDynamicSharedMemorySize, GEMM_SMEM);
    cudaFuncSetAttribute(gemm_mma<1,1>, cudaFuncAttributeMaxDynamicSharedMemorySize, GEMM_SMEM);

    const dim3 gQKV(NT/BM, QKVW/BN);  // 32 x 24 (fused q|k|v)
    const dim3 gD(NT/BM, DD/BN);      // 32 x 8
    const dim3 gF(NT/BM, FF/BN);      // 32 x 32
    const dim3 gV(NT/BM, VV/BN);      // 32 x 250

    // Launches 1-5: QKV/Wo weight converts + embed. Launch 6 = QKV GEMM (profiled).
    wconv_kernel<<<1024, 256>>>(Wq,   wh + OFF_WQ,   LL*DD*DD/16);
    wconv_kernel<<<1024, 256>>>(Wk,   wh + OFF_WK,   LL*DD*DD/16);
    wconv_kernel<<<1024, 256>>>(Wv,   wh + OFF_WV,   LL*DD*DD/16);
    wconv_kernel<<<1024, 256>>>(Wo,   wh + OFF_WO,   LL*DD*DD/16);
    embed_kernel<<<NT, 256>>>(x, emb, h, ah);

    gemm_mma<0,1><<<gQKV, 256, GEMM_SMEM>>>(ah,
        wh + OFF_WQ, wh + OFF_WK, wh + OFF_WV,
        nullptr, nullptr, qh, NT, DD, DD, QKVW);              // launch #6

    attn_kernel<<<dim3(BB * HH, SS / 64), 128>>>(qh, x, ah);

    // Remaining weight converts (before first use in layer 0 FFN / logits)
    wconv_kernel<<<2048, 256>>>(W1,   wh + OFF_W1,   LL*DD*FF/16);
    wconv_kernel<<<2048, 256>>>(W2,   wh + OFF_W2,   LL*DD*FF/16);
    wconv_kernel<<<2048, 256>>>(Wout, wh + OFF_WOUT, DD*VV/16);

    for (int l = 0; l < LL; l++) {
        const size_t oD = (size_t)l * DD * DD;
        const size_t oF = (size_t)l * DD * FF;

        if (l > 0) {
            gemm_mma<0,1><<<gQKV, 256, GEMM_SMEM>>>(ah,
                wh + OFF_WQ + oD, wh + OFF_WK + oD, wh + OFF_WV + oD,
                nullptr, nullptr, qh, NT, DD, DD, QKVW);
            attn_kernel<<<dim3(BB * HH, SS / 64), 128>>>(qh, x, ah);
        }

        gemm_mma<0,0><<<gD, 256, GEMM_SMEM>>>(ah,
            wh + OFF_WO + oD, nullptr, nullptr,
            bo + l * DD, tmp, nullptr, NT, DD, DD, DD);
        add_ln_kernel<<<NT, 256>>>(h, tmp, ln1g + l * DD, ln1b + l * DD, ah);

        gemm_mma<1,1><<<gF, 256, GEMM_SMEM>>>(ah,
            wh + OFF_W1 + oF, nullptr, nullptr,
            b1 + l * FF, nullptr, fh, NT, FF, DD, FF);
        gemm_mma<0,0><<<gD, 256, GEMM_SMEM>>>(fh,
            wh + OFF_W2 + oF, nullptr, nullptr,
            b2 + l * DD, tmp, nullptr, NT, DD, FF, DD);
        add_ln_kernel<<<NT, 256>>>(h, tmp, ln2g + l * DD, ln2b + l * DD, ah);
    }

    gemm_mma<0,0><<<gV, 256, GEMM_SMEM>>>(ah,
        wh + OFF_WOUT, nullptr, nullptr,
        bout, out, nullptr, NT, VV, DD, VV);
}